// round 1
// baseline (speedup 1.0000x reference)
#include <cuda_runtime.h>
#include <math.h>

#define NS      32768
#define NFR     128
#define WSZ     2048
#define NCHN    1024
#define MAXB    4

// ---------------- device scratch (allocation-free rule: __device__ globals) ----
__device__ float g_Wt[8*2*1024*1024];     // weights transposed to [i][k][c][o]
__device__ float g_h0[MAXB*NCHN*NFR];
__device__ float g_h1[MAXB*NCHN*NFR];
__device__ float g_enc[MAXB*256*NFR];
__device__ float g_scr[MAXB*256*NFR];
__device__ float g_vals[MAXB*16];
__device__ int   g_chv[MAXB*16];
__device__ int   g_ttv[MAXB*16];
__device__ float g_dense[MAXB*16];
__device__ float g_room[MAXB*8];
__device__ float g_mixv[MAXB];
__device__ float g_impB[MAXB*NS];
__device__ float g_dry[MAXB*NS];
__device__ float g_wet[MAXB*NS];

// ---------------- 1. weight re-layout: enc_w (8,1024,1024,2) -> Wt[i][k][c][o] --
__global__ void k_wt(const float* __restrict__ ew)
{
    __shared__ float tile[32][33];
    int ik = blockIdx.z;            // i*2+k
    int i  = ik >> 1, k = ik & 1;
    int c0 = blockIdx.x * 32, o0 = blockIdx.y * 32;
    // read: rows o, cols c (stride-2 float gather)
    for (int oo = threadIdx.y; oo < 32; oo += 8) {
        int o = o0 + oo, c = c0 + threadIdx.x;
        tile[oo][threadIdx.x] = ew[(((size_t)i*1024 + o)*1024 + c)*2 + k];
    }
    __syncthreads();
    // write: coalesced over o
    for (int cc = threadIdx.y; cc < 32; cc += 8) {
        int c = c0 + cc, o = o0 + threadIdx.x;
        g_Wt[((size_t)ik*1024 + c)*1024 + o] = tile[threadIdx.x][cc];
    }
}

// ---------------- 2. STFT magnitude (direct DFT w/ shared twiddle table) -------
// writes h[(b*1024+k)*128 + f]
__global__ void k_stft(const float* __restrict__ x)
{
    __shared__ float  w[WSZ];
    __shared__ float2 cs[WSZ];
    int f = blockIdx.x, b = blockIdx.y;
    int tid = threadIdx.x;                 // 256
    const float* xb = x + (size_t)b * NS;
    for (int n = tid; n < WSZ; n += 256) {
        int src = f * 256 + n;
        float v = (src < NS) ? xb[src] : 0.f;
        // numpy hanning: 0.5 - 0.5*cos(2*pi*n/(WS-1))
        float win = 0.5f - 0.5f * cospif(2.0f * (float)n / 2047.0f);
        w[n] = v * win;
        float s, c;
        sincospif((float)n * (1.0f/1024.0f), &s, &c);  // angle = 2*pi*n/2048
        cs[n] = make_float2(c, s);
    }
    __syncthreads();
    for (int k = tid; k < 1024; k += 256) {
        float re = 0.f, im = 0.f;
        int idx = 0;
        for (int n = 0; n < WSZ; n++) {
            float2 t = cs[idx];
            float wn = w[n];
            re += wn * t.x;
            im += wn * t.y;
            idx += k; idx &= (WSZ - 1);
        }
        g_h0[((size_t)b*1024 + k)*NFR + f] = sqrtf(re*re + im*im);
    }
}

// ---------------- 3. dilated conv layer as GEMM + residual leaky epilogue ------
// C[o,col] = sum_c W0[o,c]*H[c,t] + W1[o,c]*H[c,t+d];  hout = hin + leaky(C+b)
__global__ void k_conv(const float* __restrict__ encb, int layer, int d, int swap)
{
    const float* __restrict__ hin = swap ? g_h1 : g_h0;
    float*       __restrict__ hout = swap ? g_h0 : g_h1;
    __shared__ float As[16][64];
    __shared__ float Bs[16][64];
    int o0   = blockIdx.x * 64;
    int col0 = blockIdx.y * 64;
    int bb = col0 >> 7;
    int t0 = col0 & 127;
    int tid = threadIdx.x;
    int tx = tid & 15, ty = tid >> 4;
    float acc[4][4] = {};
    const float* Wl = g_Wt + (size_t)layer * 2 * 1024 * 1024;
    for (int kk = 0; kk < 2048; kk += 16) {
        #pragma unroll
        for (int j = 0; j < 4; j++) {
            int idx = tid + j * 256;
            int r = idx >> 6;
            int q = idx & 63;
            int kg = kk + r;
            int kp = kg >> 10;
            int c  = kg & 1023;
            As[r][q] = Wl[((size_t)kp*1024 + c)*1024 + o0 + q];
            int t = t0 + q;
            float bv;
            if (kp == 0) {
                bv = hin[((size_t)bb*1024 + c)*NFR + t];
            } else {
                int ts = t + d;
                bv = (ts < NFR) ? hin[((size_t)bb*1024 + c)*NFR + ts] : 0.f;
            }
            Bs[r][q] = bv;
        }
        __syncthreads();
        #pragma unroll
        for (int r = 0; r < 16; r++) {
            float4 a4 = *(const float4*)&As[r][ty*4];
            float4 b4 = *(const float4*)&Bs[r][tx*4];
            float av[4] = {a4.x, a4.y, a4.z, a4.w};
            float bv[4] = {b4.x, b4.y, b4.z, b4.w};
            #pragma unroll
            for (int m = 0; m < 4; m++)
                #pragma unroll
                for (int n = 0; n < 4; n++)
                    acc[m][n] += av[m] * bv[n];
        }
        __syncthreads();
    }
    #pragma unroll
    for (int m = 0; m < 4; m++) {
        int o = o0 + ty*4 + m;
        float bias = encb[layer*1024 + o];
        #pragma unroll
        for (int n = 0; n < 4; n++) {
            int col = col0 + tx*4 + n;
            int t = col & 127;
            float y  = acc[m][n] + bias;
            float ly = (y > 0.f) ? y : 0.2f * y;
            float hv = hin[((size_t)bb*1024 + o)*NFR + t];
            hout[((size_t)bb*1024 + o)*NFR + t] = hv + ly;
        }
    }
}

// ---------------- 4. z = mean_t(h); dense = unit_norm(z@lat_w + lat_b) ---------
__global__ void k_zdense(const float* __restrict__ latw, const float* __restrict__ latb)
{
    int b = blockIdx.x, tid = threadIdx.x;
    __shared__ float z[1024];
    __shared__ float dd[16];
    __shared__ float nrm;
    for (int c = tid; c < 1024; c += 256) {
        const float* hr = g_h0 + ((size_t)b*1024 + c)*NFR;
        float s = 0.f;
        #pragma unroll 8
        for (int t = 0; t < NFR; t++) s += hr[t];
        z[c] = s * (1.0f/128.0f);
    }
    __syncthreads();
    if (tid < 16) {
        float s = latb[tid];
        for (int c = 0; c < 1024; c++) s += z[c] * latw[c*16 + tid];
        dd[tid] = s;
    }
    __syncthreads();
    if (tid == 0) {
        float s = 0.f;
        for (int j = 0; j < 16; j++) s += dd[j]*dd[j];
        nrm = sqrtf(s) + 1e-8f;
    }
    __syncthreads();
    if (tid < 16) g_dense[b*16 + tid] = dd[tid] / nrm;
}

// ---------------- 5. room/mix MLPs (LinearOutputStack + softmax/sigmoid) -------
__global__ void k_mlp(const float* __restrict__ rw,  const float* __restrict__ rb,
                      const float* __restrict__ rg,  const float* __restrict__ rbe,
                      const float* __restrict__ row_,const float* __restrict__ rob,
                      const float* __restrict__ mw,  const float* __restrict__ mb2,
                      const float* __restrict__ mg,  const float* __restrict__ mbe,
                      const float* __restrict__ mow, const float* __restrict__ mob)
{
    int b = blockIdx.x, tid = threadIdx.x;   // 32 threads
    __shared__ float v[16], t0[16], stats[2];
    for (int br = 0; br < 2; br++) {
        const float* W  = br ? mw  : rw;
        const float* Bi = br ? mb2 : rb;
        const float* G  = br ? mg  : rg;
        const float* BE = br ? mbe : rbe;
        if (tid < 16) v[tid] = g_dense[b*16 + tid];
        __syncthreads();
        for (int l = 0; l < 3; l++) {
            if (tid < 16) {
                float s = Bi[l*16 + tid];
                for (int i = 0; i < 16; i++) s += v[i] * W[(l*16 + i)*16 + tid];
                t0[tid] = s;
            }
            __syncthreads();
            if (tid == 0) {
                float mu = 0.f, m2 = 0.f;
                for (int i = 0; i < 16; i++) { mu += t0[i]; m2 += t0[i]*t0[i]; }
                mu *= (1.0f/16.0f); m2 *= (1.0f/16.0f);
                stats[0] = mu; stats[1] = m2 - mu*mu;
            }
            __syncthreads();
            if (tid < 16) {
                float zz = (t0[tid] - stats[0]) * rsqrtf(stats[1] + 1e-5f) * G[l*16+tid] + BE[l*16+tid];
                v[tid] = (zz > 0.f) ? zz : 0.2f*zz;
            }
            __syncthreads();
        }
        if (br == 0) {
            if (tid < 8) {
                float s = rob[tid];
                for (int i = 0; i < 16; i++) s += v[i] * row_[i*8 + tid];
                t0[tid] = s;
            }
            __syncthreads();
            if (tid == 0) {
                float mx = -1e30f;
                for (int i = 0; i < 8; i++) mx = fmaxf(mx, t0[i]);
                float se = 0.f;
                for (int i = 0; i < 8; i++) { t0[i] = expf(t0[i] - mx); se += t0[i]; }
                for (int i = 0; i < 8; i++) g_room[b*8 + i] = t0[i] / se;
            }
            __syncthreads();
        } else {
            if (tid == 0) {
                float s = mob[0];
                for (int i = 0; i < 16; i++) s += v[i] * mow[i];
                g_mixv[b] = 1.f / (1.f + expf(-s));
            }
        }
    }
}

// ---------------- 6. enc = up_w @ h + up_b  (256x1024x128 per batch) -----------
__global__ void k_enc(const float* __restrict__ upw, const float* __restrict__ upb)
{
    int b  = blockIdx.y;
    int og = blockIdx.x * 4;
    int t  = threadIdx.x;        // 128
    __shared__ float sw[4*1024];
    for (int j = t; j < 4096; j += 128) sw[j] = upw[(size_t)og*1024 + j];
    __syncthreads();
    float a0=0.f, a1=0.f, a2=0.f, a3=0.f;
    const float* hb = g_h0 + (size_t)b*1024*NFR + t;
    for (int c = 0; c < 1024; c++) {
        float hv = hb[(size_t)c * NFR];
        a0 += sw[c]        * hv;
        a1 += sw[1024 + c] * hv;
        a2 += sw[2048 + c] * hv;
        a3 += sw[3072 + c] * hv;
    }
    g_enc[((size_t)b*256 + og + 0)*NFR + t] = a0 + upb[og+0];
    g_enc[((size_t)b*256 + og + 1)*NFR + t] = a1 + upb[og+1];
    g_enc[((size_t)b*256 + og + 2)*NFR + t] = a2 + upb[og+2];
    g_enc[((size_t)b*256 + og + 3)*NFR + t] = a3 + upb[og+3];
}

// ---------------- 7. top-16 over (256 ch x 128 frames), ties -> lowest index ---
__global__ void k_topk()
{
    int b = blockIdx.x, tid = threadIdx.x;   // 256
    float* scr = g_scr + (size_t)b * 32768;
    const float* e = g_enc + (size_t)b * 32768;
    for (int j = tid; j < 32768; j += 256) scr[j] = e[j];
    __syncthreads();
    __shared__ float bv[256];
    __shared__ int   bi[256];
    for (int it = 0; it < 16; it++) {
        float best = -1e30f; int besti = 0x7fffffff;
        for (int j = tid; j < 32768; j += 256) {
            float v = scr[j];
            if (v > best || (v == best && j < besti)) { best = v; besti = j; }
        }
        bv[tid] = best; bi[tid] = besti;
        __syncthreads();
        for (int s = 128; s > 0; s >>= 1) {
            if (tid < s) {
                if (bv[tid+s] > bv[tid] || (bv[tid+s] == bv[tid] && bi[tid+s] < bi[tid])) {
                    bv[tid] = bv[tid+s]; bi[tid] = bi[tid+s];
                }
            }
            __syncthreads();
        }
        if (tid == 0) {
            int j = bi[0]; float v = bv[0];
            // negative values lose to the zeros in the sparse array -> contribute 0
            g_vals[b*16 + it] = (v > 0.f) ? v : 0.f;
            g_chv [b*16 + it] = j >> 7;          // channel (atom index)
            g_ttv [b*16 + it] = (j & 127) * 256; // time in samples
            scr[j] = -1e30f;
        }
        __syncthreads();
    }
}

// ---------------- 8. impulse = room @ impulses ---------------------------------
__global__ void k_imp(const float* __restrict__ impulses)
{
    int b = blockIdx.y;
    int n = blockIdx.x * 256 + threadIdx.x;
    float a = 0.f;
    #pragma unroll
    for (int r = 0; r < 8; r++)
        a += g_room[b*8 + r] * impulses[(size_t)r * NS + n];
    g_impB[(size_t)b * NS + n] = a;
}

// ---------------- 9. dry = sum_k val_k * atom[ch_k] delayed by t_k -------------
__global__ void k_dry(const float* __restrict__ atoms)
{
    int b = blockIdx.y;
    int n = blockIdx.x * 256 + threadIdx.x;
    __shared__ float sv[16];
    __shared__ int   sc[16], st[16];
    if (threadIdx.x < 16) {
        sv[threadIdx.x] = g_vals[b*16 + threadIdx.x];
        sc[threadIdx.x] = g_chv [b*16 + threadIdx.x];
        st[threadIdx.x] = g_ttv [b*16 + threadIdx.x];
    }
    __syncthreads();
    float a = 0.f;
    #pragma unroll
    for (int k = 0; k < 16; k++) {
        float v = sv[k];
        if (v > 0.f) {
            int off = n - st[k];
            if (off >= 0) a += v * atoms[(size_t)sc[k] * NS + off];
        }
    }
    g_dry[(size_t)b * NS + n] = a;
}

// ---------------- 10. wet = causal linear conv(dry, impulse), tiled ------------
__global__ void k_wet()
{
    int b  = blockIdx.y;
    int n0 = blockIdx.x * 256;
    int tid = threadIdx.x;     // 256
    __shared__ float sd[256];
    __shared__ float si[512];
    const float* dryb = g_dry  + (size_t)b * NS;
    const float* impb = g_impB + (size_t)b * NS;
    float acc = 0.f;
    for (int cm = 0; cm <= n0; cm += 256) {
        __syncthreads();
        sd[tid] = dryb[cm + tid];
        int base = n0 - cm - 255;
        int u0 = base + tid;
        si[tid] = (u0 >= 0) ? impb[u0] : 0.f;
        int u1 = u0 + 256;
        si[tid + 256] = (u1 >= 0 && u1 < NS) ? impb[u1] : 0.f;
        __syncthreads();
        #pragma unroll 4
        for (int j = 0; j < 256; j += 4) {
            float4 dv = *(const float4*)&sd[j];
            acc += dv.x * si[tid + 255 - j];
            acc += dv.y * si[tid + 254 - j];
            acc += dv.z * si[tid + 253 - j];
            acc += dv.w * si[tid + 252 - j];
        }
    }
    g_wet[(size_t)b * NS + n0 + tid] = acc;
}

// ---------------- 11. out = dry*mix + wet*(1-mix) ------------------------------
__global__ void k_out(float* __restrict__ out)
{
    int b = blockIdx.y;
    int n = blockIdx.x * 256 + threadIdx.x;
    float m = g_mixv[b];
    size_t i = (size_t)b * NS + n;
    out[i] = g_dry[i] * m + g_wet[i] * (1.f - m);
}

// ---------------- launcher -----------------------------------------------------
extern "C" void kernel_launch(void* const* d_in, const int* in_sizes, int n_in,
                              void* d_out, int out_size)
{
    const float* x        = (const float*)d_in[0];
    const float* atoms    = (const float*)d_in[1];
    const float* enc_w    = (const float*)d_in[2];
    const float* enc_b    = (const float*)d_in[3];
    const float* up_w     = (const float*)d_in[4];
    const float* up_b     = (const float*)d_in[5];
    const float* lat_w    = (const float*)d_in[6];
    const float* lat_b    = (const float*)d_in[7];
    const float* room_w   = (const float*)d_in[8];
    const float* room_b   = (const float*)d_in[9];
    const float* room_g   = (const float*)d_in[10];
    const float* room_be  = (const float*)d_in[11];
    const float* room_ow  = (const float*)d_in[12];
    const float* room_ob  = (const float*)d_in[13];
    const float* mix_w    = (const float*)d_in[14];
    const float* mix_b    = (const float*)d_in[15];
    const float* mix_g    = (const float*)d_in[16];
    const float* mix_be   = (const float*)d_in[17];
    const float* mix_ow   = (const float*)d_in[18];
    const float* mix_ob   = (const float*)d_in[19];
    const float* impulses = (const float*)d_in[20];

    int B = in_sizes[0] / NS;
    if (B > MAXB) B = MAXB;
    if (B < 1)    B = 1;

    // weight re-layout (deterministic each call; ~25us)
    k_wt<<<dim3(32, 32, 16), dim3(32, 8)>>>(enc_w);

    // encode
    k_stft<<<dim3(NFR, B), 256>>>(x);
    static const int dil[8] = {1, 2, 4, 8, 16, 32, 64, 1};
    for (int l = 0; l < 8; l++) {
        k_conv<<<dim3(16, B*2), 256>>>(enc_b, l, dil[l], l & 1);
    }
    // after 8 layers (even count) final h is in g_h0

    k_zdense<<<B, 256>>>(lat_w, lat_b);
    k_mlp<<<B, 32>>>(room_w, room_b, room_g, room_be, room_ow, room_ob,
                     mix_w, mix_b, mix_g, mix_be, mix_ow, mix_ob);

    k_enc<<<dim3(64, B), 128>>>(up_w, up_b);
    k_topk<<<B, 256>>>();

    k_imp<<<dim3(NFR, B), 256>>>(impulses);
    k_dry<<<dim3(NFR, B), 256>>>(atoms);
    k_wet<<<dim3(NFR, B), 256>>>();
    k_out<<<dim3(NFR, B), 256>>>((float*)d_out);
}

// round 3
// speedup vs baseline: 2.7122x; 2.7122x over previous
#include <cuda_runtime.h>
#include <math.h>

#define NS      32768
#define NFR     128
#define WSZ     2048
#define NCHN    1024
#define MAXB    4
#define KSPLIT  4

// ---------------- device scratch (allocation-free rule: __device__ globals) ----
__device__ float g_Wt[8*2*1024*1024];     // weights transposed to [i][k][c][o]
__device__ float g_h0[MAXB*NCHN*NFR];
__device__ float g_h1[MAXB*NCHN*NFR];
__device__ float g_part[KSPLIT*NCHN*MAXB*NFR];   // GEMM K-split partials
__device__ float g_enc[MAXB*256*NFR];
__device__ float g_vals[MAXB*16];
__device__ int   g_chv[MAXB*16];
__device__ int   g_ttv[MAXB*16];
__device__ float g_dense[MAXB*16];
__device__ float g_room[MAXB*8];
__device__ float g_mixv[MAXB];
__device__ float g_impB[MAXB*NS];
__device__ float g_dry[MAXB*NS];
__device__ float g_wetp[4*MAXB*NS];              // wet conv partials (4 segments)

// ---------------- 1. weight re-layout: enc_w (8,1024,1024,2) -> Wt[i][k][c][o] --
__global__ void k_wt(const float* __restrict__ ew)
{
    __shared__ float tile[32][33];
    int ik = blockIdx.z;            // i*2+k
    int i  = ik >> 1, k = ik & 1;
    int c0 = blockIdx.x * 32, o0 = blockIdx.y * 32;
    for (int oo = threadIdx.y; oo < 32; oo += 8) {
        int o = o0 + oo, c = c0 + threadIdx.x;
        tile[oo][threadIdx.x] = ew[(((size_t)i*1024 + o)*1024 + c)*2 + k];
    }
    __syncthreads();
    for (int cc = threadIdx.y; cc < 32; cc += 8) {
        int c = c0 + cc, o = o0 + threadIdx.x;
        g_Wt[((size_t)ik*1024 + c)*1024 + o] = tile[threadIdx.x][cc];
    }
}

// ---------------- 2. STFT magnitude (direct DFT, 1 bin/thread) -----------------
// grid (NFR, 4, B), 256 threads; writes h[(b*1024+k)*128 + f]
__global__ void k_stft(const float* __restrict__ x)
{
    __shared__ float  w[WSZ];
    __shared__ float2 cs[WSZ];
    int f = blockIdx.x, b = blockIdx.z;
    int tid = threadIdx.x;                 // 256
    const float* xb = x + (size_t)b * NS;
    for (int n = tid; n < WSZ; n += 256) {
        int src = f * 256 + n;
        float v = (src < NS) ? xb[src] : 0.f;
        float win = 0.5f - 0.5f * cospif(2.0f * (float)n / 2047.0f);
        w[n] = v * win;
        float s, c;
        sincospif((float)n * (1.0f/1024.0f), &s, &c);
        cs[n] = make_float2(c, s);
    }
    __syncthreads();
    int k = blockIdx.y * 256 + tid;
    float re = 0.f, im = 0.f;
    int idx = 0;
    #pragma unroll 8
    for (int n = 0; n < WSZ; n++) {
        float2 t = cs[idx];
        float wn = w[n];
        re += wn * t.x;
        im += wn * t.y;
        idx += k; idx &= (WSZ - 1);
    }
    g_h0[((size_t)b*1024 + k)*NFR + f] = sqrtf(re*re + im*im);
}

// ---------------- 3a. dilated conv layer GEMM, K-split partials ----------------
// grid (16 o-tiles, B*2 col-tiles, KSPLIT); 64x64 tile over K range of 512
__global__ void __launch_bounds__(256) k_conv_part(int layer, int d, int swap, int COLS)
{
    const float* __restrict__ hin = swap ? g_h1 : g_h0;
    __shared__ float As[16][64];
    __shared__ float Bs[16][64];
    int o0   = blockIdx.x * 64;
    int col0 = blockIdx.y * 64;
    int ks   = blockIdx.z;
    int bb = col0 >> 7;
    int t0 = col0 & 127;
    int tid = threadIdx.x;
    int tx = tid & 15, ty = tid >> 4;
    float acc[4][4] = {};
    const float* Wl = g_Wt + (size_t)layer * 2 * 1024 * 1024;
    int k0 = ks * 512;
    for (int kk = k0; kk < k0 + 512; kk += 16) {
        #pragma unroll
        for (int j = 0; j < 4; j++) {
            int idx = tid + j * 256;
            int r = idx >> 6;
            int q = idx & 63;
            int kg = kk + r;
            int kp = kg >> 10;
            int c  = kg & 1023;
            As[r][q] = Wl[((size_t)kp*1024 + c)*1024 + o0 + q];
            int t = t0 + q;
            float bv;
            if (kp == 0) {
                bv = hin[((size_t)bb*1024 + c)*NFR + t];
            } else {
                int ts = t + d;
                bv = (ts < NFR) ? hin[((size_t)bb*1024 + c)*NFR + ts] : 0.f;
            }
            Bs[r][q] = bv;
        }
        __syncthreads();
        #pragma unroll
        for (int r = 0; r < 16; r++) {
            float4 a4 = *(const float4*)&As[r][ty*4];
            float4 b4 = *(const float4*)&Bs[r][tx*4];
            float av[4] = {a4.x, a4.y, a4.z, a4.w};
            float bv[4] = {b4.x, b4.y, b4.z, b4.w};
            #pragma unroll
            for (int m = 0; m < 4; m++)
                #pragma unroll
                for (int n = 0; n < 4; n++)
                    acc[m][n] += av[m] * bv[n];
        }
        __syncthreads();
    }
    #pragma unroll
    for (int m = 0; m < 4; m++) {
        int o = o0 + ty*4 + m;
        #pragma unroll
        for (int n = 0; n < 4; n++) {
            int col = col0 + tx*4 + n;
            g_part[((size_t)ks*1024 + o)*COLS + col] = acc[m][n];
        }
    }
}

// ---------------- 3b. epilogue: sum partials + bias + leaky + residual ---------
// grid (1024, B), 128 threads
__global__ void k_conv_epi(const float* __restrict__ encb, int layer, int swap, int COLS)
{
    const float* __restrict__ hin  = swap ? g_h1 : g_h0;
    float*       __restrict__ hout = swap ? g_h0 : g_h1;
    int o = blockIdx.x, b = blockIdx.y, t = threadIdx.x;
    int col = b * NFR + t;
    float s = 0.f;
    #pragma unroll
    for (int ks = 0; ks < KSPLIT; ks++)
        s += g_part[((size_t)ks*1024 + o)*COLS + col];
    float y  = s + encb[layer*1024 + o];
    float ly = (y > 0.f) ? y : 0.2f * y;
    size_t hi = ((size_t)b*1024 + o)*NFR + t;
    hout[hi] = hin[hi] + ly;
}

// ---------------- 4. z = mean_t(h); dense = unit_norm(z@lat_w + lat_b) ---------
__global__ void k_zdense(const float* __restrict__ latw, const float* __restrict__ latb)
{
    int b = blockIdx.x, tid = threadIdx.x;
    __shared__ float z[1024];
    __shared__ float dd[16];
    __shared__ float nrm;
    for (int c = tid; c < 1024; c += 256) {
        const float* hr = g_h0 + ((size_t)b*1024 + c)*NFR;
        float s = 0.f;
        #pragma unroll 8
        for (int t = 0; t < NFR; t++) s += hr[t];
        z[c] = s * (1.0f/128.0f);
    }
    __syncthreads();
    if (tid < 16) {
        float s = latb[tid];
        for (int c = 0; c < 1024; c++) s += z[c] * latw[c*16 + tid];
        dd[tid] = s;
    }
    __syncthreads();
    if (tid == 0) {
        float s = 0.f;
        for (int j = 0; j < 16; j++) s += dd[j]*dd[j];
        nrm = sqrtf(s) + 1e-8f;
    }
    __syncthreads();
    if (tid < 16) g_dense[b*16 + tid] = dd[tid] / nrm;
}

// ---------------- 5. room/mix MLPs ---------------------------------------------
__global__ void k_mlp(const float* __restrict__ rw,  const float* __restrict__ rb,
                      const float* __restrict__ rg,  const float* __restrict__ rbe,
                      const float* __restrict__ row_,const float* __restrict__ rob,
                      const float* __restrict__ mw,  const float* __restrict__ mb2,
                      const float* __restrict__ mg,  const float* __restrict__ mbe,
                      const float* __restrict__ mow, const float* __restrict__ mob)
{
    int b = blockIdx.x, tid = threadIdx.x;   // 32 threads
    __shared__ float v[16], t0[16], stats[2];
    for (int br = 0; br < 2; br++) {
        const float* W  = br ? mw  : rw;
        const float* Bi = br ? mb2 : rb;
        const float* G  = br ? mg  : rg;
        const float* BE = br ? mbe : rbe;
        if (tid < 16) v[tid] = g_dense[b*16 + tid];
        __syncthreads();
        for (int l = 0; l < 3; l++) {
            if (tid < 16) {
                float s = Bi[l*16 + tid];
                for (int i = 0; i < 16; i++) s += v[i] * W[(l*16 + i)*16 + tid];
                t0[tid] = s;
            }
            __syncthreads();
            if (tid == 0) {
                float mu = 0.f, m2 = 0.f;
                for (int i = 0; i < 16; i++) { mu += t0[i]; m2 += t0[i]*t0[i]; }
                mu *= (1.0f/16.0f); m2 *= (1.0f/16.0f);
                stats[0] = mu; stats[1] = m2 - mu*mu;
            }
            __syncthreads();
            if (tid < 16) {
                float zz = (t0[tid] - stats[0]) * rsqrtf(stats[1] + 1e-5f) * G[l*16+tid] + BE[l*16+tid];
                v[tid] = (zz > 0.f) ? zz : 0.2f*zz;
            }
            __syncthreads();
        }
        if (br == 0) {
            if (tid < 8) {
                float s = rob[tid];
                for (int i = 0; i < 16; i++) s += v[i] * row_[i*8 + tid];
                t0[tid] = s;
            }
            __syncthreads();
            if (tid == 0) {
                float mx = -1e30f;
                for (int i = 0; i < 8; i++) mx = fmaxf(mx, t0[i]);
                float se = 0.f;
                for (int i = 0; i < 8; i++) { t0[i] = expf(t0[i] - mx); se += t0[i]; }
                for (int i = 0; i < 8; i++) g_room[b*8 + i] = t0[i] / se;
            }
            __syncthreads();
        } else {
            if (tid == 0) {
                float s = mob[0];
                for (int i = 0; i < 16; i++) s += v[i] * mow[i];
                g_mixv[b] = 1.f / (1.f + expf(-s));
            }
        }
    }
}

// ---------------- 6. enc = up_w @ h + up_b  ------------------------------------
__global__ void k_enc(const float* __restrict__ upw, const float* __restrict__ upb)
{
    int b  = blockIdx.y;
    int og = blockIdx.x * 4;
    int t  = threadIdx.x;        // 128
    __shared__ float sw[4*1024];
    for (int j = t; j < 4096; j += 128) sw[j] = upw[(size_t)og*1024 + j];
    __syncthreads();
    float a0=0.f, a1=0.f, a2=0.f, a3=0.f;
    const float* hb = g_h0 + (size_t)b*1024*NFR + t;
    for (int c = 0; c < 1024; c++) {
        float hv = hb[(size_t)c * NFR];
        a0 += sw[c]        * hv;
        a1 += sw[1024 + c] * hv;
        a2 += sw[2048 + c] * hv;
        a3 += sw[3072 + c] * hv;
    }
    g_enc[((size_t)b*256 + og + 0)*NFR + t] = a0 + upb[og+0];
    g_enc[((size_t)b*256 + og + 1)*NFR + t] = a1 + upb[og+1];
    g_enc[((size_t)b*256 + og + 2)*NFR + t] = a2 + upb[og+2];
    g_enc[((size_t)b*256 + og + 3)*NFR + t] = a3 + upb[og+3];
}

// ---------------- 7. top-16 via shared-memory scans ----------------------------
// grid B, 1024 threads, 128KB dynamic smem
__global__ void k_topk()
{
    extern __shared__ float scr[];           // 32768 floats
    __shared__ float bv[1024];
    __shared__ int   bi[1024];
    int b = blockIdx.x, tid = threadIdx.x;
    const float* e = g_enc + (size_t)b * 32768;
    for (int j = tid; j < 32768; j += 1024) scr[j] = e[j];
    __syncthreads();
    for (int it = 0; it < 16; it++) {
        float best = -1e30f; int besti = 0x7fffffff;
        #pragma unroll
        for (int i = 0; i < 32; i++) {
            int j = tid + i * 1024;
            float v = scr[j];
            if (v > best || (v == best && j < besti)) { best = v; besti = j; }
        }
        bv[tid] = best; bi[tid] = besti;
        __syncthreads();
        for (int s = 512; s > 0; s >>= 1) {
            if (tid < s) {
                if (bv[tid+s] > bv[tid] || (bv[tid+s] == bv[tid] && bi[tid+s] < bi[tid])) {
                    bv[tid] = bv[tid+s]; bi[tid] = bi[tid+s];
                }
            }
            __syncthreads();
        }
        if (tid == 0) {
            int j = bi[0]; float v = bv[0];
            // negatives lose to the zeros of the 8.4M-entry sparse array -> 0
            g_vals[b*16 + it] = (v > 0.f) ? v : 0.f;
            g_chv [b*16 + it] = j >> 7;
            g_ttv [b*16 + it] = (j & 127) * 256;
            scr[j] = -1e30f;
        }
        __syncthreads();
    }
}

// ---------------- 8. impulse = room @ impulses ---------------------------------
__global__ void k_imp(const float* __restrict__ impulses)
{
    int b = blockIdx.y;
    int n = blockIdx.x * 256 + threadIdx.x;
    float a = 0.f;
    #pragma unroll
    for (int r = 0; r < 8; r++)
        a += g_room[b*8 + r] * impulses[(size_t)r * NS + n];
    g_impB[(size_t)b * NS + n] = a;
}

// ---------------- 9. dry = sum_k val_k * atom[ch_k] delayed by t_k -------------
__global__ void k_dry(const float* __restrict__ atoms)
{
    int b = blockIdx.y;
    int n = blockIdx.x * 256 + threadIdx.x;
    __shared__ float sv[16];
    __shared__ int   sc[16], st[16];
    if (threadIdx.x < 16) {
        sv[threadIdx.x] = g_vals[b*16 + threadIdx.x];
        sc[threadIdx.x] = g_chv [b*16 + threadIdx.x];
        st[threadIdx.x] = g_ttv [b*16 + threadIdx.x];
    }
    __syncthreads();
    float a = 0.f;
    #pragma unroll
    for (int k = 0; k < 16; k++) {
        float v = sv[k];
        if (v > 0.f) {
            int off = n - st[k];
            if (off >= 0) a += v * atoms[(size_t)sc[k] * NS + off];
        }
    }
    g_dry[(size_t)b * NS + n] = a;
}

// ---------------- 10. wet = causal conv(dry, impulse), 4-way history split -----
// grid (128 out-tiles, 4 segments, B), 256 threads; partials into g_wetp
__global__ void k_wet()
{
    int bx = blockIdx.x, s = blockIdx.y, b = blockIdx.z;
    int n0 = bx * 256;
    int tid = threadIdx.x;
    __shared__ float sd[256];
    __shared__ float si[512];
    const float* dryb = g_dry  + (size_t)b * NS;
    const float* impb = g_impB + (size_t)b * NS;
    float acc = 0.f;
    int c0 = s * 32;
    int c1 = min(c0 + 32, bx + 1);
    for (int c = c0; c < c1; c++) {
        int cm = c * 256;
        __syncthreads();
        sd[tid] = dryb[cm + tid];
        int base = n0 - cm - 255;
        int u0 = base + tid;
        si[tid] = (u0 >= 0) ? impb[u0] : 0.f;
        int u1 = u0 + 256;
        si[tid + 256] = (u1 >= 0 && u1 < NS) ? impb[u1] : 0.f;
        __syncthreads();
        #pragma unroll 4
        for (int j = 0; j < 256; j += 4) {
            float4 dv = *(const float4*)&sd[j];
            acc += dv.x * si[tid + 255 - j];
            acc += dv.y * si[tid + 254 - j];
            acc += dv.z * si[tid + 253 - j];
            acc += dv.w * si[tid + 252 - j];
        }
    }
    g_wetp[((size_t)s*MAXB + b)*NS + n0 + tid] = acc;
}

// ---------------- 11. out = dry*mix + (sum wet partials)*(1-mix) ---------------
__global__ void k_out(float* __restrict__ out)
{
    int b = blockIdx.y;
    int n = blockIdx.x * 256 + threadIdx.x;
    float m = g_mixv[b];
    size_t i = (size_t)b * NS + n;
    float wet = g_wetp[((size_t)0*MAXB + b)*NS + n]
              + g_wetp[((size_t)1*MAXB + b)*NS + n]
              + g_wetp[((size_t)2*MAXB + b)*NS + n]
              + g_wetp[((size_t)3*MAXB + b)*NS + n];
    out[i] = g_dry[i] * m + wet * (1.f - m);
}

// ---------------- launcher -----------------------------------------------------
extern "C" void kernel_launch(void* const* d_in, const int* in_sizes, int n_in,
                              void* d_out, int out_size)
{
    const float* x        = (const float*)d_in[0];
    const float* atoms    = (const float*)d_in[1];
    const float* enc_w    = (const float*)d_in[2];
    const float* enc_b    = (const float*)d_in[3];
    const float* up_w     = (const float*)d_in[4];
    const float* up_b     = (const float*)d_in[5];
    const float* lat_w    = (const float*)d_in[6];
    const float* lat_b    = (const float*)d_in[7];
    const float* room_w   = (const float*)d_in[8];
    const float* room_b   = (const float*)d_in[9];
    const float* room_g   = (const float*)d_in[10];
    const float* room_be  = (const float*)d_in[11];
    const float* room_ow  = (const float*)d_in[12];
    const float* room_ob  = (const float*)d_in[13];
    const float* mix_w    = (const float*)d_in[14];
    const float* mix_b    = (const float*)d_in[15];
    const float* mix_g    = (const float*)d_in[16];
    const float* mix_be   = (const float*)d_in[17];
    const float* mix_ow   = (const float*)d_in[18];
    const float* mix_ob   = (const float*)d_in[19];
    const float* impulses = (const float*)d_in[20];

    int B = in_sizes[0] / NS;
    if (B > MAXB) B = MAXB;
    if (B < 1)    B = 1;
    int COLS = B * NFR;

    // no static guard (determinism rule): idempotent, non-stream API call
    cudaFuncSetAttribute(k_topk, cudaFuncAttributeMaxDynamicSharedMemorySize, 131072);

    k_wt<<<dim3(32, 32, 16), dim3(32, 8)>>>(enc_w);

    k_stft<<<dim3(NFR, 4, B), 256>>>(x);
    static const int dil[8] = {1, 2, 4, 8, 16, 32, 64, 1};
    for (int l = 0; l < 8; l++) {
        k_conv_part<<<dim3(16, B*2, KSPLIT), 256>>>(l, dil[l], l & 1, COLS);
        k_conv_epi<<<dim3(1024, B), 128>>>(enc_b, l, l & 1, COLS);
    }
    // after 8 layers (even count) final h is in g_h0

    k_zdense<<<B, 256>>>(lat_w, lat_b);
    k_mlp<<<B, 32>>>(room_w, room_b, room_g, room_be, room_ow, room_ob,
                     mix_w, mix_b, mix_g, mix_be, mix_ow, mix_ob);

    k_enc<<<dim3(64, B), 128>>>(up_w, up_b);
    k_topk<<<B, 1024, 131072>>>();

    k_imp<<<dim3(NFR, B), 256>>>(impulses);
    k_dry<<<dim3(NFR, B), 256>>>(atoms);
    k_wet<<<dim3(NFR, 4, B), 256>>>();
    k_out<<<dim3(NFR, B), 256>>>((float*)d_out);
}